// round 1
// baseline (speedup 1.0000x reference)
#include <cuda_runtime.h>
#include <math.h>

// Problem constants (fixed shapes for GCM_60490319396973)
constexpr int N_   = 40000;
constexpr int DIM_ = 256;
constexpr int H_   = 128;
constexpr int K_   = 27;
constexpr int B_   = 4;
constexpr int KH_  = K_ * H_;      // 3456
constexpr int NPART = 250;
constexpr int CHUNK = (N_ + NPART - 1) / NPART;   // 160

// ---------------- scratch (device globals: no allocation allowed) ----------
__device__ float g_convx[(N_ + 1) * H_];   // padded: row N_ is the zero row
__device__ float g_glo  [(N_ + 1) * H_];
__device__ float g_r1   [(N_ + 1) * H_];
__device__ float g_convout[N_ * H_];
__device__ float g_f1[N_ * H_];
__device__ float g_f2[N_ * H_];
__device__ float g_t [N_ * H_];
__device__ float g_part[NPART * B_ * H_];
__device__ int   g_cnt [NPART * B_];
__device__ float g_m2  [B_ * H_];

// ---------------- tiny kernels ---------------------------------------------
__global__ void zero_pad_kernel() {
    int t = threadIdx.x;                 // 128 threads
    g_convx[N_ * H_ + t] = 0.f;
    g_glo  [N_ * H_ + t] = 0.f;
    g_r1   [N_ * H_ + t] = 0.f;
}

// ---------------- generic tiled GEMM ---------------------------------------
// C[m,n] = epilogue( bias[n] + sum_k A[m,k] * B[k,n] )
// A modes: dense (lda), gathered rows via nbr (sconv), concat of two H-wide bufs
enum { AM_DENSE = 0, AM_GATHER = 1, AM_CONCAT = 2 };
enum { EP_SPLIT = 0, EP_RELU = 1, EP_R2 = 2, EP_GLO = 3, EP_FINAL = 4 };

constexpr int TILE = 128;
constexpr int BK   = 16;

template <int AMODE, int EPI>
__global__ void __launch_bounds__(256, 2)
gemm_kernel(const float* __restrict__ A, const float* __restrict__ A2,
            const int* __restrict__ nbr,
            const float* __restrict__ Bm, int ldb, int Kdim, int lda,
            const float* __restrict__ bias,
            const float* __restrict__ aux,
            float* __restrict__ C, float* __restrict__ C2)
{
    __shared__ float As[BK][TILE];
    __shared__ float Bs[BK][TILE];
    __shared__ int   snbr[TILE * K_];

    const int tid = threadIdx.x;
    const int m0  = blockIdx.x * TILE;
    const int n0  = blockIdx.y * TILE;

    if (AMODE == AM_GATHER) {
        for (int i = tid; i < TILE * K_; i += 256) {
            int r = i / K_, k = i % K_;
            int row = m0 + r;
            snbr[i] = (row < N_) ? nbr[row * K_ + k] : N_;   // N_ -> zero row
        }
        __syncthreads();
    }

    float acc[8][8];
#pragma unroll
    for (int i = 0; i < 8; i++)
#pragma unroll
        for (int j = 0; j < 8; j++) acc[i][j] = 0.f;

    const int tr = tid >> 4;      // 0..15
    const int tc = tid & 15;      // 0..15

    for (int k0 = 0; k0 < Kdim; k0 += BK) {
        // ---- stage A tile (128 rows x 16 cols), stored transposed ----
#pragma unroll
        for (int it = 0; it < 2; it++) {
            int idx = tid + it * 256;
            int r   = idx >> 2;
            int c4  = (idx & 3) << 2;
            float4 v = make_float4(0.f, 0.f, 0.f, 0.f);
            if (AMODE == AM_GATHER) {
                int kidx = k0 >> 7;                 // which neighbor slot
                int cc   = (k0 & 127) + c4;         // feature within row
                int src  = snbr[r * K_ + kidx];
                v = *reinterpret_cast<const float4*>(A + (size_t)src * H_ + cc);
            } else if (AMODE == AM_DENSE) {
                int row = m0 + r;
                if (row < N_)
                    v = *reinterpret_cast<const float4*>(A + (size_t)row * lda + k0 + c4);
            } else {  // AM_CONCAT
                int row = m0 + r;
                int g   = k0 + c4;
                if (row < N_) {
                    const float* src = (g < H_) ? A : A2;
                    int gc = (g < H_) ? g : g - H_;
                    v = *reinterpret_cast<const float4*>(src + (size_t)row * H_ + gc);
                }
            }
            As[c4 + 0][r] = v.x;
            As[c4 + 1][r] = v.y;
            As[c4 + 2][r] = v.z;
            As[c4 + 3][r] = v.w;
        }
        // ---- stage B tile (16 rows x 128 cols) ----
#pragma unroll
        for (int it = 0; it < 2; it++) {
            int idx = tid + it * 256;
            int r   = idx >> 5;
            int c4  = (idx & 31) << 2;
            float4 v = *reinterpret_cast<const float4*>(
                Bm + (size_t)(k0 + r) * ldb + n0 + c4);
            *reinterpret_cast<float4*>(&Bs[r][c4]) = v;
        }
        __syncthreads();

        // ---- 128x128x16 compute, 8x8 per thread ----
#pragma unroll
        for (int c = 0; c < BK; c++) {
            float a[8], b[8];
#pragma unroll
            for (int i = 0; i < 8; i++) a[i] = As[c][tr * 8 + i];
#pragma unroll
            for (int j = 0; j < 8; j++) b[j] = Bs[c][tc * 8 + j];
#pragma unroll
            for (int i = 0; i < 8; i++)
#pragma unroll
                for (int j = 0; j < 8; j++)
                    acc[i][j] = fmaf(a[i], b[j], acc[i][j]);
        }
        __syncthreads();
    }

    // ---- epilogue ----
#pragma unroll
    for (int i = 0; i < 8; i++) {
        int row = m0 + tr * 8 + i;
        if (row >= N_) continue;
#pragma unroll
        for (int j = 0; j < 8; j++) {
            int col = n0 + tc * 8 + j;
            float v = acc[i][j] + bias[col];
            if (EPI == EP_SPLIT) {
                if (col < H_) C [(size_t)row * H_ + col]      = v;
                else          C2[(size_t)row * H_ + col - H_] = v;
            } else if (EPI == EP_RELU) {
                C[(size_t)row * H_ + col] = fmaxf(v, 0.f);
            } else if (EPI == EP_R2) {
                C[(size_t)row * H_ + col] =
                    fmaxf(v, 0.f) + 2.f * aux[(size_t)row * H_ + col];
            } else if (EPI == EP_GLO) {
                float g = aux[(size_t)row * H_ + col];
                C[(size_t)row * H_ + col] = fmaxf(g - fmaxf(v, 0.f), 0.f);
            } else {  // EP_FINAL
                C[(size_t)row * DIM_ + col] =
                    aux[(size_t)row * DIM_ + col] + v;
            }
        }
    }
}

// ---------------- deterministic segment mean (m2) ---------------------------
__global__ void seg_partial_kernel(const int* __restrict__ bids) {
    int blk = blockIdx.x;
    int o   = threadIdx.x;            // 128 threads = one column each
    int r0  = blk * CHUNK;
    int r1  = min(r0 + CHUNK, N_);
    float a0 = 0.f, a1 = 0.f, a2 = 0.f, a3 = 0.f;
    for (int r = r0; r < r1; r++) {
        int   b = bids[r];
        float v = g_f2[(size_t)r * H_ + o];
        a0 += (b == 0) ? v : 0.f;
        a1 += (b == 1) ? v : 0.f;
        a2 += (b == 2) ? v : 0.f;
        a3 += (b == 3) ? v : 0.f;
    }
    g_part[(blk * B_ + 0) * H_ + o] = a0;
    g_part[(blk * B_ + 1) * H_ + o] = a1;
    g_part[(blk * B_ + 2) * H_ + o] = a2;
    g_part[(blk * B_ + 3) * H_ + o] = a3;
    if (o < B_) {
        int c = 0;
        for (int r = r0; r < r1; r++) c += (bids[r] == o);
        g_cnt[blk * B_ + o] = c;
    }
}

__global__ void seg_final_kernel() {
    int t = threadIdx.x;              // 512 threads = (b,o)
    float s = 0.f;
    for (int p = 0; p < NPART; p++) s += g_part[p * B_ * H_ + t];
    __shared__ int scnt[B_];
    if (t < B_) {
        int c = 0;
        for (int p = 0; p < NPART; p++) c += g_cnt[p * B_ + t];
        scnt[t] = c;
    }
    __syncthreads();
    int b = t / H_;
    float cnt = (float)max(scnt[b], 1);
    g_m2[t] = s / cnt;
}

// ---------------- enc / t = enc + f1 + f2 -----------------------------------
__global__ void enc_kernel(const int* __restrict__ bids) {
    int warp = threadIdx.x >> 5;      // 4 warps -> 4 rows per block
    int lane = threadIdx.x & 31;
    int row  = blockIdx.x * 4 + warp;

    float4 f1v = reinterpret_cast<const float4*>(g_f1 + (size_t)row * H_)[lane];
    float s = f1v.x + f1v.y + f1v.z + f1v.w;
#pragma unroll
    for (int off = 16; off; off >>= 1) s += __shfl_xor_sync(0xffffffffu, s, off);
    float row1 = s * (1.f / 128.f);

    int b = bids[row];
    float4 f2v = reinterpret_cast<const float4*>(g_f2 + (size_t)row * H_)[lane];
    float4 m2v = reinterpret_cast<const float4*>(g_m2 + b * H_)[lane];

    float4 t;
    t.x = sqrtf(row1 * m2v.x + 1e-12f) + f1v.x + f2v.x;
    t.y = sqrtf(row1 * m2v.y + 1e-12f) + f1v.y + f2v.y;
    t.z = sqrtf(row1 * m2v.z + 1e-12f) + f1v.z + f2v.z;
    t.w = sqrtf(row1 * m2v.w + 1e-12f) + f1v.w + f2v.w;
    reinterpret_cast<float4*>(g_t + (size_t)row * H_)[lane] = t;
}

// ---------------- launch ----------------------------------------------------
extern "C" void kernel_launch(void* const* d_in, const int* in_sizes, int n_in,
                              void* d_out, int out_size)
{
    const float* x    = (const float*)d_in[0];
    const int*   nbr  = (const int*)  d_in[1];
    const int*   bids = (const int*)  d_in[2];
    const float* W1   = (const float*)d_in[3];
    const float* b1   = (const float*)d_in[4];
    const float* W2   = (const float*)d_in[5];
    const float* b2   = (const float*)d_in[6];
    const float* Wr1  = (const float*)d_in[7];
    const float* br1  = (const float*)d_in[8];
    const float* Wr2  = (const float*)d_in[9];
    const float* br2  = (const float*)d_in[10];
    const float* Wg1  = (const float*)d_in[11];
    const float* bg1  = (const float*)d_in[12];
    const float* Wg2  = (const float*)d_in[13];
    const float* bg2  = (const float*)d_in[14];
    const float* Wg3  = (const float*)d_in[15];
    const float* bg3  = (const float*)d_in[16];
    float* out = (float*)d_out;

    float *convx, *glo, *r1, *convout, *f1, *f2, *tb;
    cudaGetSymbolAddress((void**)&convx,   g_convx);
    cudaGetSymbolAddress((void**)&glo,     g_glo);
    cudaGetSymbolAddress((void**)&r1,      g_r1);
    cudaGetSymbolAddress((void**)&convout, g_convout);
    cudaGetSymbolAddress((void**)&f1,      g_f1);
    cudaGetSymbolAddress((void**)&f2,      g_f2);
    cudaGetSymbolAddress((void**)&tb,      g_t);

    const int mt = (N_ + TILE - 1) / TILE;   // 313
    dim3 blk(256);

    // zero the padding row of all gathered buffers
    zero_pad_kernel<<<1, 128>>>();

    // h = x@W1 + b1 ; conv_x = h[:, :128] ; glo = h[:, 128:]
    gemm_kernel<AM_DENSE, EP_SPLIT><<<dim3(mt, 2), blk>>>(
        x, nullptr, nullptr, W1, DIM_, DIM_, DIM_, b1, nullptr, convx, glo);

    // r1 = relu(sconv(conv_x, Wr1, br1))
    gemm_kernel<AM_GATHER, EP_RELU><<<dim3(mt, 1), blk>>>(
        convx, nullptr, nbr, Wr1, H_, KH_, 0, br1, nullptr, r1, nullptr);

    // convout = relu(sconv(r1, Wr2, br2)) + 2*conv_x
    gemm_kernel<AM_GATHER, EP_R2><<<dim3(mt, 1), blk>>>(
        r1, nullptr, nbr, Wr2, H_, KH_, 0, br2, convx, convout, nullptr);

    // f1 = relu(sconv(glo, Wg1, bg1)) ; f2 = relu(sconv(glo, Wg2, bg2))
    gemm_kernel<AM_GATHER, EP_RELU><<<dim3(mt, 1), blk>>>(
        glo, nullptr, nbr, Wg1, H_, KH_, 0, bg1, nullptr, f1, nullptr);
    gemm_kernel<AM_GATHER, EP_RELU><<<dim3(mt, 1), blk>>>(
        glo, nullptr, nbr, Wg2, H_, KH_, 0, bg2, nullptr, f2, nullptr);

    // m2 = segment_mean(f2) (deterministic two-pass)
    seg_partial_kernel<<<NPART, 128>>>(bids);
    seg_final_kernel<<<1, 512>>>();

    // t = sqrt(mean(f1)*m2[bid] + 1e-12) + f1 + f2
    enc_kernel<<<N_ / 4, 128>>>(bids);

    // glo = relu(glo - relu(t@Wg3 + bg3))
    gemm_kernel<AM_DENSE, EP_GLO><<<dim3(mt, 1), blk>>>(
        tb, nullptr, nullptr, Wg3, H_, H_, H_, bg3, glo, glo, nullptr);

    // out = x + [convout | glo] @ W2 + b2
    gemm_kernel<AM_CONCAT, EP_FINAL><<<dim3(mt, 2), blk>>>(
        convout, glo, nullptr, W2, DIM_, DIM_, 0, b2, x, out, nullptr);
}

// round 2
// speedup vs baseline: 2.2914x; 2.2914x over previous
#include <cuda_runtime.h>
#include <math.h>
#include <stdint.h>

// Problem constants (fixed shapes for GCM_60490319396973)
constexpr int N_   = 40000;
constexpr int DIM_ = 256;
constexpr int H_   = 128;
constexpr int K_   = 27;
constexpr int B_   = 4;
constexpr int KH_  = K_ * H_;      // 3456
constexpr int NPART = 250;
constexpr int CHUNK = (N_ + NPART - 1) / NPART;   // 160

// ---------------- scratch (device globals: no allocation allowed) ----------
__device__ float g_convx[(N_ + 1) * H_];   // padded: row N_ is the zero row
__device__ float g_glo  [(N_ + 1) * H_];
__device__ float g_r1   [(N_ + 1) * H_];
__device__ float g_convout[N_ * H_];
__device__ float g_f1[N_ * H_];
__device__ float g_f2[N_ * H_];
__device__ float g_t [N_ * H_];
__device__ float g_part[NPART * B_ * H_];
__device__ int   g_cnt [NPART * B_];
__device__ float g_m2  [B_ * H_];

// ---------------- tiny kernels ---------------------------------------------
__global__ void zero_pad_kernel() {
    int t = threadIdx.x;                 // 128 threads
    g_convx[N_ * H_ + t] = 0.f;
    g_glo  [N_ * H_ + t] = 0.f;
    g_r1   [N_ * H_ + t] = 0.f;
}

// ---------------- tf32 helpers ----------------------------------------------
__device__ __forceinline__ uint32_t f2tf32(float x) {
    uint32_t y;
    asm("cvt.rna.tf32.f32 %0, %1;" : "=r"(y) : "f"(x));
    return y;
}

__device__ __forceinline__ void mma_tf32(float c[4], const uint32_t a[4],
                                         const uint32_t b[2]) {
    asm volatile(
        "mma.sync.aligned.m16n8k8.row.col.f32.tf32.tf32.f32 "
        "{%0,%1,%2,%3}, {%4,%5,%6,%7}, {%8,%9}, {%0,%1,%2,%3};\n"
        : "+f"(c[0]), "+f"(c[1]), "+f"(c[2]), "+f"(c[3])
        : "r"(a[0]), "r"(a[1]), "r"(a[2]), "r"(a[3]), "r"(b[0]), "r"(b[1]));
}

// ---------------- generic tiled tf32 tensor-core GEMM -----------------------
// C[m,n] = epilogue( bias[n] + sum_k A[m,k] * B[k,n] )
enum { AM_DENSE = 0, AM_GATHER = 1, AM_CONCAT = 2 };
enum { EP_SPLIT = 0, EP_RELU = 1, EP_R2 = 2, EP_GLO = 3, EP_FINAL = 4 };

constexpr int TILE = 128;
constexpr int BK   = 16;
constexpr int PA   = BK + 4;     // A smem pitch (floats): 20 -> conflict-free frag reads
constexpr int PB   = TILE + 8;   // B smem pitch (floats): 136 -> conflict-free frag reads

template <int AMODE, int EPI>
__global__ void __launch_bounds__(256, 2)
gemm_kernel(const float* __restrict__ A, const float* __restrict__ A2,
            const int* __restrict__ nbr,
            const float* __restrict__ Bm, int ldb, int Kdim, int lda,
            const float* __restrict__ bias,
            const float* __restrict__ aux,
            float* __restrict__ C, float* __restrict__ C2)
{
    __shared__ uint32_t As[TILE * PA];     // [m][k], pitch 20
    __shared__ uint32_t Bs[BK * PB];       // [k][n], pitch 136
    __shared__ int      snbr[TILE * K_];

    const int tid = threadIdx.x;
    const int m0  = blockIdx.x * TILE;
    const int n0  = blockIdx.y * TILE;

    const int lane = tid & 31;
    const int wid  = tid >> 5;         // 0..7
    const int wm   = wid & 3;          // warp row  (4 x 32 = 128)
    const int wn   = wid >> 2;         // warp col  (2 x 64 = 128)
    const int g    = lane >> 2;        // group 0..7
    const int tg   = lane & 3;         // thread-in-group 0..3

    if (AMODE == AM_GATHER) {
        for (int i = tid; i < TILE * K_; i += 256) {
            int r = i / K_, k = i % K_;
            int row = m0 + r;
            snbr[i] = (row < N_) ? nbr[row * K_ + k] : N_;   // N_ -> zero row
        }
        __syncthreads();
    }

    float acc[2][8][4];
#pragma unroll
    for (int mt = 0; mt < 2; mt++)
#pragma unroll
        for (int nt = 0; nt < 8; nt++)
#pragma unroll
            for (int j = 0; j < 4; j++) acc[mt][nt][j] = 0.f;

    for (int k0 = 0; k0 < Kdim; k0 += BK) {
        // ---- stage A tile (128 rows x 16 cols), row-major, pitch PA ----
#pragma unroll
        for (int it = 0; it < 2; it++) {
            int idx = tid + it * 256;
            int r   = idx >> 2;            // 0..127
            int c4  = (idx & 3) << 2;      // 0,4,8,12
            float4 v = make_float4(0.f, 0.f, 0.f, 0.f);
            if (AMODE == AM_GATHER) {
                int kidx = k0 >> 7;                 // which neighbor slot
                int cc   = (k0 & 127) + c4;         // feature within row
                int src  = snbr[r * K_ + kidx];
                v = *reinterpret_cast<const float4*>(A + (size_t)src * H_ + cc);
            } else if (AMODE == AM_DENSE) {
                int row = m0 + r;
                if (row < N_)
                    v = *reinterpret_cast<const float4*>(A + (size_t)row * lda + k0 + c4);
            } else {  // AM_CONCAT
                int row = m0 + r;
                int gc  = k0 + c4;
                if (row < N_) {
                    const float* src = (gc < H_) ? A : A2;
                    int cc = (gc < H_) ? gc : gc - H_;
                    v = *reinterpret_cast<const float4*>(src + (size_t)row * H_ + cc);
                }
            }
            uint4 t;
            t.x = f2tf32(v.x); t.y = f2tf32(v.y);
            t.z = f2tf32(v.z); t.w = f2tf32(v.w);
            *reinterpret_cast<uint4*>(&As[r * PA + c4]) = t;
        }
        // ---- stage B tile (16 rows x 128 cols), pitch PB ----
#pragma unroll
        for (int it = 0; it < 2; it++) {
            int idx = tid + it * 256;
            int r   = idx >> 5;            // 0..15
            int c4  = (idx & 31) << 2;     // 0..124
            float4 v = *reinterpret_cast<const float4*>(
                Bm + (size_t)(k0 + r) * ldb + n0 + c4);
            uint4 t;
            t.x = f2tf32(v.x); t.y = f2tf32(v.y);
            t.z = f2tf32(v.z); t.w = f2tf32(v.w);
            *reinterpret_cast<uint4*>(&Bs[r * PB + c4]) = t;
        }
        __syncthreads();

        // ---- 128x128x16 compute via m16n8k8 tf32 MMA ----
#pragma unroll
        for (int ks = 0; ks < BK; ks += 8) {
            uint32_t bfr[8][2];
#pragma unroll
            for (int nt = 0; nt < 8; nt++) {
                int n = wn * 64 + nt * 8 + g;
                bfr[nt][0] = Bs[(ks + tg)     * PB + n];
                bfr[nt][1] = Bs[(ks + tg + 4) * PB + n];
            }
#pragma unroll
            for (int mt = 0; mt < 2; mt++) {
                int m = wm * 32 + mt * 16 + g;
                uint32_t af[4];
                af[0] = As[m       * PA + ks + tg];
                af[1] = As[(m + 8) * PA + ks + tg];
                af[2] = As[m       * PA + ks + tg + 4];
                af[3] = As[(m + 8) * PA + ks + tg + 4];
#pragma unroll
                for (int nt = 0; nt < 8; nt++)
                    mma_tf32(acc[mt][nt], af, bfr[nt]);
            }
        }
        __syncthreads();
    }

    // ---- epilogue: each thread owns 2x(2 rows) x 8x(2 cols) ----
#pragma unroll
    for (int mt = 0; mt < 2; mt++) {
#pragma unroll
        for (int half = 0; half < 2; half++) {
            int row = m0 + wm * 32 + mt * 16 + g + half * 8;
            if (row >= N_) continue;
#pragma unroll
            for (int nt = 0; nt < 8; nt++) {
                int col = n0 + wn * 64 + nt * 8 + tg * 2;
                float v0 = acc[mt][nt][half * 2 + 0] + bias[col];
                float v1 = acc[mt][nt][half * 2 + 1] + bias[col + 1];
                if (EPI == EP_SPLIT) {
                    if (col < H_) {
                        C [(size_t)row * H_ + col]     = v0;
                        C [(size_t)row * H_ + col + 1] = v1;
                    } else {
                        C2[(size_t)row * H_ + col - H_]     = v0;
                        C2[(size_t)row * H_ + col - H_ + 1] = v1;
                    }
                } else if (EPI == EP_RELU) {
                    float2 o = make_float2(fmaxf(v0, 0.f), fmaxf(v1, 0.f));
                    *reinterpret_cast<float2*>(C + (size_t)row * H_ + col) = o;
                } else if (EPI == EP_R2) {
                    float2 a = *reinterpret_cast<const float2*>(
                        aux + (size_t)row * H_ + col);
                    float2 o = make_float2(fmaxf(v0, 0.f) + 2.f * a.x,
                                           fmaxf(v1, 0.f) + 2.f * a.y);
                    *reinterpret_cast<float2*>(C + (size_t)row * H_ + col) = o;
                } else if (EPI == EP_GLO) {
                    float2 a = *reinterpret_cast<const float2*>(
                        aux + (size_t)row * H_ + col);
                    float2 o = make_float2(fmaxf(a.x - fmaxf(v0, 0.f), 0.f),
                                           fmaxf(a.y - fmaxf(v1, 0.f), 0.f));
                    *reinterpret_cast<float2*>(C + (size_t)row * H_ + col) = o;
                } else {  // EP_FINAL
                    float2 a = *reinterpret_cast<const float2*>(
                        aux + (size_t)row * DIM_ + col);
                    float2 o = make_float2(a.x + v0, a.y + v1);
                    *reinterpret_cast<float2*>(C + (size_t)row * DIM_ + col) = o;
                }
            }
        }
    }
}

// ---------------- deterministic segment mean (m2) ---------------------------
__global__ void seg_partial_kernel(const int* __restrict__ bids) {
    int blk = blockIdx.x;
    int o   = threadIdx.x;            // 128 threads = one column each
    int r0  = blk * CHUNK;
    int r1  = min(r0 + CHUNK, N_);
    float a0 = 0.f, a1 = 0.f, a2 = 0.f, a3 = 0.f;
    for (int r = r0; r < r1; r++) {
        int   b = bids[r];
        float v = g_f2[(size_t)r * H_ + o];
        a0 += (b == 0) ? v : 0.f;
        a1 += (b == 1) ? v : 0.f;
        a2 += (b == 2) ? v : 0.f;
        a3 += (b == 3) ? v : 0.f;
    }
    g_part[(blk * B_ + 0) * H_ + o] = a0;
    g_part[(blk * B_ + 1) * H_ + o] = a1;
    g_part[(blk * B_ + 2) * H_ + o] = a2;
    g_part[(blk * B_ + 3) * H_ + o] = a3;
    if (o < B_) {
        int c = 0;
        for (int r = r0; r < r1; r++) c += (bids[r] == o);
        g_cnt[blk * B_ + o] = c;
    }
}

__global__ void seg_final_kernel() {
    int t = threadIdx.x;              // 512 threads = (b,o)
    float s = 0.f;
    for (int p = 0; p < NPART; p++) s += g_part[p * B_ * H_ + t];
    __shared__ int scnt[B_];
    if (t < B_) {
        int c = 0;
        for (int p = 0; p < NPART; p++) c += g_cnt[p * B_ + t];
        scnt[t] = c;
    }
    __syncthreads();
    int b = t / H_;
    float cnt = (float)max(scnt[b], 1);
    g_m2[t] = s / cnt;
}

// ---------------- enc / t = enc + f1 + f2 -----------------------------------
__global__ void enc_kernel(const int* __restrict__ bids) {
    int warp = threadIdx.x >> 5;      // 4 warps -> 4 rows per block
    int lane = threadIdx.x & 31;
    int row  = blockIdx.x * 4 + warp;

    float4 f1v = reinterpret_cast<const float4*>(g_f1 + (size_t)row * H_)[lane];
    float s = f1v.x + f1v.y + f1v.z + f1v.w;
#pragma unroll
    for (int off = 16; off; off >>= 1) s += __shfl_xor_sync(0xffffffffu, s, off);
    float row1 = s * (1.f / 128.f);

    int b = bids[row];
    float4 f2v = reinterpret_cast<const float4*>(g_f2 + (size_t)row * H_)[lane];
    float4 m2v = reinterpret_cast<const float4*>(g_m2 + b * H_)[lane];

    float4 t;
    t.x = sqrtf(row1 * m2v.x + 1e-12f) + f1v.x + f2v.x;
    t.y = sqrtf(row1 * m2v.y + 1e-12f) + f1v.y + f2v.y;
    t.z = sqrtf(row1 * m2v.z + 1e-12f) + f1v.z + f2v.z;
    t.w = sqrtf(row1 * m2v.w + 1e-12f) + f1v.w + f2v.w;
    reinterpret_cast<float4*>(g_t + (size_t)row * H_)[lane] = t;
}

// ---------------- launch ----------------------------------------------------
extern "C" void kernel_launch(void* const* d_in, const int* in_sizes, int n_in,
                              void* d_out, int out_size)
{
    const float* x    = (const float*)d_in[0];
    const int*   nbr  = (const int*)  d_in[1];
    const int*   bids = (const int*)  d_in[2];
    const float* W1   = (const float*)d_in[3];
    const float* b1   = (const float*)d_in[4];
    const float* W2   = (const float*)d_in[5];
    const float* b2   = (const float*)d_in[6];
    const float* Wr1  = (const float*)d_in[7];
    const float* br1  = (const float*)d_in[8];
    const float* Wr2  = (const float*)d_in[9];
    const float* br2  = (const float*)d_in[10];
    const float* Wg1  = (const float*)d_in[11];
    const float* bg1  = (const float*)d_in[12];
    const float* Wg2  = (const float*)d_in[13];
    const float* bg2  = (const float*)d_in[14];
    const float* Wg3  = (const float*)d_in[15];
    const float* bg3  = (const float*)d_in[16];
    float* out = (float*)d_out;

    float *convx, *glo, *r1, *convout, *f1, *f2, *tb;
    cudaGetSymbolAddress((void**)&convx,   g_convx);
    cudaGetSymbolAddress((void**)&glo,     g_glo);
    cudaGetSymbolAddress((void**)&r1,      g_r1);
    cudaGetSymbolAddress((void**)&convout, g_convout);
    cudaGetSymbolAddress((void**)&f1,      g_f1);
    cudaGetSymbolAddress((void**)&f2,      g_f2);
    cudaGetSymbolAddress((void**)&tb,      g_t);

    const int mt = (N_ + TILE - 1) / TILE;   // 313
    dim3 blk(256);

    // zero the padding row of all gathered buffers
    zero_pad_kernel<<<1, 128>>>();

    // h = x@W1 + b1 ; conv_x = h[:, :128] ; glo = h[:, 128:]
    gemm_kernel<AM_DENSE, EP_SPLIT><<<dim3(mt, 2), blk>>>(
        x, nullptr, nullptr, W1, DIM_, DIM_, DIM_, b1, nullptr, convx, glo);

    // r1 = relu(sconv(conv_x, Wr1, br1))
    gemm_kernel<AM_GATHER, EP_RELU><<<dim3(mt, 1), blk>>>(
        convx, nullptr, nbr, Wr1, H_, KH_, 0, br1, nullptr, r1, nullptr);

    // convout = relu(sconv(r1, Wr2, br2)) + 2*conv_x
    gemm_kernel<AM_GATHER, EP_R2><<<dim3(mt, 1), blk>>>(
        r1, nullptr, nbr, Wr2, H_, KH_, 0, br2, convx, convout, nullptr);

    // f1 = relu(sconv(glo, Wg1, bg1)) ; f2 = relu(sconv(glo, Wg2, bg2))
    gemm_kernel<AM_GATHER, EP_RELU><<<dim3(mt, 1), blk>>>(
        glo, nullptr, nbr, Wg1, H_, KH_, 0, bg1, nullptr, f1, nullptr);
    gemm_kernel<AM_GATHER, EP_RELU><<<dim3(mt, 1), blk>>>(
        glo, nullptr, nbr, Wg2, H_, KH_, 0, bg2, nullptr, f2, nullptr);

    // m2 = segment_mean(f2) (deterministic two-pass)
    seg_partial_kernel<<<NPART, 128>>>(bids);
    seg_final_kernel<<<1, 512>>>();

    // t = sqrt(mean(f1)*m2[bid] + 1e-12) + f1 + f2
    enc_kernel<<<N_ / 4, 128>>>(bids);

    // glo = relu(glo - relu(t@Wg3 + bg3))
    gemm_kernel<AM_DENSE, EP_GLO><<<dim3(mt, 1), blk>>>(
        tb, nullptr, nullptr, Wg3, H_, H_, H_, bg3, glo, glo, nullptr);

    // out = x + [convout | glo] @ W2 + b2
    gemm_kernel<AM_CONCAT, EP_FINAL><<<dim3(mt, 2), blk>>>(
        convout, glo, nullptr, W2, DIM_, DIM_, 0, b2, x, out, nullptr);
}

// round 4
// speedup vs baseline: 3.3550x; 1.4641x over previous
#include <cuda_runtime.h>
#include <math.h>
#include <stdint.h>

// Problem constants (fixed shapes for GCM_60490319396973)
constexpr int N_   = 40000;
constexpr int DIM_ = 256;
constexpr int H_   = 128;
constexpr int K_   = 27;
constexpr int B_   = 4;
constexpr int KH_  = K_ * H_;      // 3456
constexpr int NPART = 250;
constexpr int CHUNK = (N_ + NPART - 1) / NPART;   // 160

// ---------------- scratch (device globals: no allocation allowed) ----------
__device__ float g_convx[(N_ + 1) * H_];   // padded: row N_ is the zero row
__device__ float g_glo  [(N_ + 1) * H_];
__device__ float g_r1   [(N_ + 1) * H_];
__device__ float g_convout[N_ * H_];
__device__ float g_f1[N_ * H_];
__device__ float g_f2[N_ * H_];
__device__ float g_t [N_ * H_];
__device__ float g_part[NPART * B_ * H_];
__device__ int   g_cnt [NPART * B_];
__device__ float g_m2  [B_ * H_];

// ---------------- tiny kernels ---------------------------------------------
__global__ void zero_pad_kernel() {
    int t = threadIdx.x;                 // 128 threads
    g_convx[N_ * H_ + t] = 0.f;
    g_glo  [N_ * H_ + t] = 0.f;
    g_r1   [N_ * H_ + t] = 0.f;
}

// ---------------- tf32 / async helpers --------------------------------------
__device__ __forceinline__ uint32_t f2tf32(float x) {
    uint32_t y;
    asm("cvt.rna.tf32.f32 %0, %1;" : "=r"(y) : "f"(x));
    return y;
}

__device__ __forceinline__ void mma_tf32(float c[4], const uint32_t a[4],
                                         const uint32_t b[2]) {
    asm volatile(
        "mma.sync.aligned.m16n8k8.row.col.f32.tf32.tf32.f32 "
        "{%0,%1,%2,%3}, {%4,%5,%6,%7}, {%8,%9}, {%0,%1,%2,%3};\n"
        : "+f"(c[0]), "+f"(c[1]), "+f"(c[2]), "+f"(c[3])
        : "r"(a[0]), "r"(a[1]), "r"(a[2]), "r"(a[3]), "r"(b[0]), "r"(b[1]));
}

__device__ __forceinline__ void cp16(uint32_t dst, const void* src, bool valid) {
    asm volatile("cp.async.cg.shared.global [%0], [%1], 16, %2;"
                 :: "r"(dst), "l"(src), "r"(valid ? 16 : 0));
}
__device__ __forceinline__ void cp_commit() {
    asm volatile("cp.async.commit_group;");
}
__device__ __forceinline__ void cp_wait0() {
    asm volatile("cp.async.wait_group 0;");
}

// ---------------- generic tiled tf32 tensor-core GEMM -----------------------
// C[m,n] = epilogue( bias[n] + sum_k A[m,k] * B[k,n] )
enum { AM_DENSE = 0, AM_GATHER = 1, AM_CONCAT = 2 };
enum { EP_SPLIT = 0, EP_RELU = 1, EP_R2 = 2, EP_GLO = 3, EP_FINAL = 4 };

constexpr int TILE = 128;
constexpr int BK   = 32;
constexpr int PA   = BK + 4;     // 36 floats: conflict-free frag reads, 16B-aligned rows
constexpr int PB   = TILE + 8;   // 136 floats

constexpr int SMEM_BYTES = 2 * TILE * PA * 4   // As double-buffered (raw fp32)
                         + 2 * BK * PB * 4     // Bs double-buffered
                         + TILE * K_ * 4;      // snbr

template <int AMODE, int EPI>
__global__ void __launch_bounds__(256, 2)
gemm_kernel(const float* __restrict__ A, const float* __restrict__ A2,
            const int* __restrict__ nbr,
            const float* __restrict__ Bm, int ldb, int Kdim, int lda,
            const float* __restrict__ bias,
            const float* __restrict__ aux,
            float* __restrict__ C, float* __restrict__ C2)
{
    extern __shared__ char smem_raw[];
    float* As   = reinterpret_cast<float*>(smem_raw);            // [2][128][PA]
    float* Bs   = As + 2 * TILE * PA;                            // [2][32][PB]
    int*   snbr = reinterpret_cast<int*>(Bs + 2 * BK * PB);      // [128][27]

    const int tid = threadIdx.x;
    const int m0  = blockIdx.x * TILE;
    const int n0  = blockIdx.y * TILE;

    const int lane = tid & 31;
    const int wid  = tid >> 5;         // 0..7
    const int wm   = wid & 3;          // warp row  (4 x 32 = 128)
    const int wn   = wid >> 2;         // warp col  (2 x 64 = 128)
    const int g    = lane >> 2;        // group 0..7
    const int tg   = lane & 3;         // thread-in-group 0..3

    if (AMODE == AM_GATHER) {
        for (int i = tid; i < TILE * K_; i += 256) {
            int r = i / K_, k = i % K_;
            int row = m0 + r;
            snbr[i] = (row < N_) ? nbr[row * K_ + k] : N_;   // N_ -> zero row
        }
        __syncthreads();
    }

    // --- stage one (A,B) tile pair into buffer `buf` via cp.async -----------
    auto stage = [&](int k0, int buf) {
        float* Ab = As + buf * TILE * PA;
        float* Bb = Bs + buf * BK * PB;
        // A tile: 128 rows x 32 cols = 1024 float4
#pragma unroll
        for (int it = 0; it < 4; it++) {
            int idx = tid + it * 256;
            int r   = idx >> 3;            // 0..127
            int c4  = (idx & 7) << 2;      // 0..28
            uint32_t dst = (uint32_t)__cvta_generic_to_shared(&Ab[r * PA + c4]);
            if (AMODE == AM_GATHER) {
                int kidx = k0 >> 7;                 // neighbor slot (BK=32 -> 4 iters/slot)
                int cc   = (k0 & 127) + c4;
                int src  = snbr[r * K_ + kidx];
                cp16(dst, A + (size_t)src * H_ + cc, true);
            } else if (AMODE == AM_DENSE) {
                int row = m0 + r;
                cp16(dst, A + (size_t)row * lda + k0 + c4, row < N_);
            } else {  // AM_CONCAT
                int row = m0 + r;
                int gc  = k0 + c4;
                const float* srcp = (gc < H_) ? A : A2;
                int cc = (gc < H_) ? gc : gc - H_;
                cp16(dst, srcp + (size_t)row * H_ + cc, row < N_);
            }
        }
        // B tile: 32 rows x 128 cols = 1024 float4
#pragma unroll
        for (int it = 0; it < 4; it++) {
            int idx = tid + it * 256;
            int r   = idx >> 5;            // 0..31
            int c4  = (idx & 31) << 2;     // 0..124
            uint32_t dst = (uint32_t)__cvta_generic_to_shared(&Bb[r * PB + c4]);
            cp16(dst, Bm + (size_t)(k0 + r) * ldb + n0 + c4, true);
        }
    };

    float acc[2][8][4];
#pragma unroll
    for (int mt = 0; mt < 2; mt++)
#pragma unroll
        for (int nt = 0; nt < 8; nt++)
#pragma unroll
            for (int j = 0; j < 4; j++) acc[mt][nt][j] = 0.f;

    const int niter = Kdim / BK;

    stage(0, 0);
    cp_commit();

    int buf = 0;
    for (int i = 0; i < niter; i++) {
        cp_wait0();
        __syncthreads();
        if (i + 1 < niter) {
            stage((i + 1) * BK, buf ^ 1);
            cp_commit();
        }

        const float* Ab = As + buf * TILE * PA;
        const float* Bb = Bs + buf * BK * PB;
#pragma unroll
        for (int ks = 0; ks < BK; ks += 8) {
            uint32_t bfr[8][2];
#pragma unroll
            for (int nt = 0; nt < 8; nt++) {
                int n = wn * 64 + nt * 8 + g;
                bfr[nt][0] = f2tf32(Bb[(ks + tg)     * PB + n]);
                bfr[nt][1] = f2tf32(Bb[(ks + tg + 4) * PB + n]);
            }
#pragma unroll
            for (int mt = 0; mt < 2; mt++) {
                int m = wm * 32 + mt * 16 + g;
                uint32_t af[4];
                af[0] = f2tf32(Ab[m       * PA + ks + tg]);
                af[1] = f2tf32(Ab[(m + 8) * PA + ks + tg]);
                af[2] = f2tf32(Ab[m       * PA + ks + tg + 4]);
                af[3] = f2tf32(Ab[(m + 8) * PA + ks + tg + 4]);
#pragma unroll
                for (int nt = 0; nt < 8; nt++)
                    mma_tf32(acc[mt][nt], af, bfr[nt]);
            }
        }
        buf ^= 1;
    }

    // ---- epilogue: each thread owns 2x(2 rows) x 8x(2 cols) ----
#pragma unroll
    for (int mt = 0; mt < 2; mt++) {
#pragma unroll
        for (int half = 0; half < 2; half++) {
            int row = m0 + wm * 32 + mt * 16 + g + half * 8;
            if (row >= N_) continue;
#pragma unroll
            for (int nt = 0; nt < 8; nt++) {
                int col = n0 + wn * 64 + nt * 8 + tg * 2;
                float v0 = acc[mt][nt][half * 2 + 0] + bias[col];
                float v1 = acc[mt][nt][half * 2 + 1] + bias[col + 1];
                if (EPI == EP_SPLIT) {
                    if (col < H_) {
                        C [(size_t)row * H_ + col]     = v0;
                        C [(size_t)row * H_ + col + 1] = v1;
                    } else {
                        C2[(size_t)row * H_ + col - H_]     = v0;
                        C2[(size_t)row * H_ + col - H_ + 1] = v1;
                    }
                } else if (EPI == EP_RELU) {
                    float2 o = make_float2(fmaxf(v0, 0.f), fmaxf(v1, 0.f));
                    *reinterpret_cast<float2*>(C + (size_t)row * H_ + col) = o;
                } else if (EPI == EP_R2) {
                    float2 a = *reinterpret_cast<const float2*>(
                        aux + (size_t)row * H_ + col);
                    float2 o = make_float2(fmaxf(v0, 0.f) + 2.f * a.x,
                                           fmaxf(v1, 0.f) + 2.f * a.y);
                    *reinterpret_cast<float2*>(C + (size_t)row * H_ + col) = o;
                } else if (EPI == EP_GLO) {
                    float2 a = *reinterpret_cast<const float2*>(
                        aux + (size_t)row * H_ + col);
                    float2 o = make_float2(fmaxf(a.x - fmaxf(v0, 0.f), 0.f),
                                           fmaxf(a.y - fmaxf(v1, 0.f), 0.f));
                    *reinterpret_cast<float2*>(C + (size_t)row * H_ + col) = o;
                } else {  // EP_FINAL
                    float2 a = *reinterpret_cast<const float2*>(
                        aux + (size_t)row * DIM_ + col);
                    float2 o = make_float2(a.x + v0, a.y + v1);
                    *reinterpret_cast<float2*>(C + (size_t)row * DIM_ + col) = o;
                }
            }
        }
    }
}

// ---------------- deterministic segment mean (m2) ---------------------------
__global__ void seg_partial_kernel(const int* __restrict__ bids) {
    int blk = blockIdx.x;
    int o   = threadIdx.x;            // 128 threads = one column each
    int r0  = blk * CHUNK;
    int r1  = min(r0 + CHUNK, N_);
    float a0 = 0.f, a1 = 0.f, a2 = 0.f, a3 = 0.f;
    for (int r = r0; r < r1; r++) {
        int   b = bids[r];
        float v = g_f2[(size_t)r * H_ + o];
        a0 += (b == 0) ? v : 0.f;
        a1 += (b == 1) ? v : 0.f;
        a2 += (b == 2) ? v : 0.f;
        a3 += (b == 3) ? v : 0.f;
    }
    g_part[(blk * B_ + 0) * H_ + o] = a0;
    g_part[(blk * B_ + 1) * H_ + o] = a1;
    g_part[(blk * B_ + 2) * H_ + o] = a2;
    g_part[(blk * B_ + 3) * H_ + o] = a3;
    if (o < B_) {
        int c = 0;
        for (int r = r0; r < r1; r++) c += (bids[r] == o);
        g_cnt[blk * B_ + o] = c;
    }
}

__global__ void seg_final_kernel() {
    int t = threadIdx.x;              // 512 threads = (b,o)
    float s = 0.f;
    for (int p = 0; p < NPART; p++) s += g_part[p * B_ * H_ + t];
    __shared__ int scnt[B_];
    if (t < B_) {
        int c = 0;
        for (int p = 0; p < NPART; p++) c += g_cnt[p * B_ + t];
        scnt[t] = c;
    }
    __syncthreads();
    int b = t / H_;
    float cnt = (float)max(scnt[b], 1);
    g_m2[t] = s / cnt;
}

// ---------------- enc / t = enc + f1 + f2 -----------------------------------
__global__ void enc_kernel(const int* __restrict__ bids) {
    int warp = threadIdx.x >> 5;      // 4 warps -> 4 rows per block
    int lane = threadIdx.x & 31;
    int row  = blockIdx.x * 4 + warp;

    float4 f1v = reinterpret_cast<const float4*>(g_f1 + (size_t)row * H_)[lane];
    float s = f1v.x + f1v.y + f1v.z + f1v.w;
#pragma unroll
    for (int off = 16; off; off >>= 1) s += __shfl_xor_sync(0xffffffffu, s, off);
    float row1 = s * (1.f / 128.f);

    int b = bids[row];
    float4 f2v = reinterpret_cast<const float4*>(g_f2 + (size_t)row * H_)[lane];
    float4 m2v = reinterpret_cast<const float4*>(g_m2 + b * H_)[lane];

    float4 t;
    t.x = sqrtf(row1 * m2v.x + 1e-12f) + f1v.x + f2v.x;
    t.y = sqrtf(row1 * m2v.y + 1e-12f) + f1v.y + f2v.y;
    t.z = sqrtf(row1 * m2v.z + 1e-12f) + f1v.z + f2v.z;
    t.w = sqrtf(row1 * m2v.w + 1e-12f) + f1v.w + f2v.w;
    reinterpret_cast<float4*>(g_t + (size_t)row * H_)[lane] = t;
}

// ---------------- launch ----------------------------------------------------
extern "C" void kernel_launch(void* const* d_in, const int* in_sizes, int n_in,
                              void* d_out, int out_size)
{
    const float* x    = (const float*)d_in[0];
    const int*   nbr  = (const int*)  d_in[1];
    const int*   bids = (const int*)  d_in[2];
    const float* W1   = (const float*)d_in[3];
    const float* b1   = (const float*)d_in[4];
    const float* W2   = (const float*)d_in[5];
    const float* b2   = (const float*)d_in[6];
    const float* Wr1  = (const float*)d_in[7];
    const float* br1  = (const float*)d_in[8];
    const float* Wr2  = (const float*)d_in[9];
    const float* br2  = (const float*)d_in[10];
    const float* Wg1  = (const float*)d_in[11];
    const float* bg1  = (const float*)d_in[12];
    const float* Wg2  = (const float*)d_in[13];
    const float* bg2  = (const float*)d_in[14];
    const float* Wg3  = (const float*)d_in[15];
    const float* bg3  = (const float*)d_in[16];
    float* out = (float*)d_out;

    float *convx, *glo, *r1, *convout, *f1, *f2, *tb;
    cudaGetSymbolAddress((void**)&convx,   g_convx);
    cudaGetSymbolAddress((void**)&glo,     g_glo);
    cudaGetSymbolAddress((void**)&r1,      g_r1);
    cudaGetSymbolAddress((void**)&convout, g_convout);
    cudaGetSymbolAddress((void**)&f1,      g_f1);
    cudaGetSymbolAddress((void**)&f2,      g_f2);
    cudaGetSymbolAddress((void**)&tb,      g_t);

    // allow >48KB dynamic smem on every instantiation (idempotent, host-side)
    cudaFuncSetAttribute(gemm_kernel<AM_DENSE,  EP_SPLIT>,
                         cudaFuncAttributeMaxDynamicSharedMemorySize, SMEM_BYTES);
    cudaFuncSetAttribute(gemm_kernel<AM_GATHER, EP_RELU>,
                         cudaFuncAttributeMaxDynamicSharedMemorySize, SMEM_BYTES);
    cudaFuncSetAttribute(gemm_kernel<AM_GATHER, EP_R2>,
                         cudaFuncAttributeMaxDynamicSharedMemorySize, SMEM_BYTES);
    cudaFuncSetAttribute(gemm_kernel<AM_DENSE,  EP_GLO>,
                         cudaFuncAttributeMaxDynamicSharedMemorySize, SMEM_BYTES);
    cudaFuncSetAttribute(gemm_kernel<AM_CONCAT, EP_FINAL>,
                         cudaFuncAttributeMaxDynamicSharedMemorySize, SMEM_BYTES);

    const int mt = (N_ + TILE - 1) / TILE;   // 313
    dim3 blk(256);

    // zero the padding row of all gathered buffers
    zero_pad_kernel<<<1, 128>>>();

    // h = x@W1 + b1 ; conv_x = h[:, :128] ; glo = h[:, 128:]
    gemm_kernel<AM_DENSE, EP_SPLIT><<<dim3(mt, 2), blk, SMEM_BYTES>>>(
        x, nullptr, nullptr, W1, DIM_, DIM_, DIM_, b1, nullptr, convx, glo);

    // r1 = relu(sconv(conv_x, Wr1, br1))
    gemm_kernel<AM_GATHER, EP_RELU><<<dim3(mt, 1), blk, SMEM_BYTES>>>(
        convx, nullptr, nbr, Wr1, H_, KH_, 0, br1, nullptr, r1, nullptr);

    // convout = relu(sconv(r1, Wr2, br2)) + 2*conv_x
    gemm_kernel<AM_GATHER, EP_R2><<<dim3(mt, 1), blk, SMEM_BYTES>>>(
        r1, nullptr, nbr, Wr2, H_, KH_, 0, br2, convx, convout, nullptr);

    // f1 = relu(sconv(glo, Wg1, bg1)) ; f2 = relu(sconv(glo, Wg2, bg2))
    gemm_kernel<AM_GATHER, EP_RELU><<<dim3(mt, 1), blk, SMEM_BYTES>>>(
        glo, nullptr, nbr, Wg1, H_, KH_, 0, bg1, nullptr, f1, nullptr);
    gemm_kernel<AM_GATHER, EP_RELU><<<dim3(mt, 1), blk, SMEM_BYTES>>>(
        glo, nullptr, nbr, Wg2, H_, KH_, 0, bg2, nullptr, f2, nullptr);

    // m2 = segment_mean(f2) (deterministic two-pass)
    seg_partial_kernel<<<NPART, 128>>>(bids);
    seg_final_kernel<<<1, 512>>>();

    // t = sqrt(mean(f1)*m2[bid] + 1e-12) + f1 + f2
    enc_kernel<<<N_ / 4, 128>>>(bids);

    // glo = relu(glo - relu(t@Wg3 + bg3))
    gemm_kernel<AM_DENSE, EP_GLO><<<dim3(mt, 1), blk, SMEM_BYTES>>>(
        tb, nullptr, nullptr, Wg3, H_, H_, H_, bg3, glo, glo, nullptr);

    // out = x + [convout | glo] @ W2 + b2
    gemm_kernel<AM_CONCAT, EP_FINAL><<<dim3(mt, 2), blk, SMEM_BYTES>>>(
        convout, glo, nullptr, W2, DIM_, DIM_, 0, b2, x, out, nullptr);
}

// round 5
// speedup vs baseline: 3.7794x; 1.1265x over previous
#include <cuda_runtime.h>
#include <math.h>
#include <stdint.h>

// Problem constants (fixed shapes for GCM_60490319396973)
constexpr int N_   = 40000;
constexpr int DIM_ = 256;
constexpr int H_   = 128;
constexpr int K_   = 27;
constexpr int B_   = 4;
constexpr int KH_  = K_ * H_;      // 3456
constexpr int NPART = 250;
constexpr int CHUNK = (N_ + NPART - 1) / NPART;   // 160

// ---------------- scratch (device globals: no allocation allowed) ----------
__device__ float g_convx[(N_ + 1) * H_];   // padded: row N_ is the zero row
__device__ float g_glo  [(N_ + 1) * H_];
__device__ float g_r1   [(N_ + 1) * H_];
__device__ float g_convout[N_ * H_];
__device__ float g_f1[N_ * H_];
__device__ float g_f2[N_ * H_];
__device__ float g_t [N_ * H_];
__device__ float g_part[NPART * B_ * H_];
__device__ int   g_cnt [NPART * B_];
__device__ float g_m2  [B_ * H_];
// tf32-pre-rounded operand copies
__device__ float g_xr  [N_ * DIM_];
__device__ float g_W1r [DIM_ * DIM_];
__device__ float g_W2r [DIM_ * DIM_];
__device__ float g_Wr1r[KH_ * H_];
__device__ float g_Wr2r[KH_ * H_];
__device__ float g_Wg1r[KH_ * H_];
__device__ float g_Wg2r[KH_ * H_];
__device__ float g_Wg3r[H_ * H_];

// ---------------- tf32 / async helpers --------------------------------------
__device__ __forceinline__ uint32_t f2tf32(float x) {
    uint32_t y;
    asm("cvt.rna.tf32.f32 %0, %1;" : "=r"(y) : "f"(x));
    return y;
}
__device__ __forceinline__ float rnd_tf32(float x) {
    return __uint_as_float(f2tf32(x));
}

__device__ __forceinline__ void mma_tf32(float c[4], const uint32_t a[4],
                                         const uint32_t b[2]) {
    asm volatile(
        "mma.sync.aligned.m16n8k8.row.col.f32.tf32.tf32.f32 "
        "{%0,%1,%2,%3}, {%4,%5,%6,%7}, {%8,%9}, {%0,%1,%2,%3};\n"
        : "+f"(c[0]), "+f"(c[1]), "+f"(c[2]), "+f"(c[3])
        : "r"(a[0]), "r"(a[1]), "r"(a[2]), "r"(a[3]), "r"(b[0]), "r"(b[1]));
}

__device__ __forceinline__ void cp16(uint32_t dst, const void* src, bool valid) {
    asm volatile("cp.async.cg.shared.global [%0], [%1], 16, %2;"
                 :: "r"(dst), "l"(src), "r"(valid ? 16 : 0));
}
__device__ __forceinline__ void cp_commit() {
    asm volatile("cp.async.commit_group;");
}
__device__ __forceinline__ void cp_wait0() {
    asm volatile("cp.async.wait_group 0;");
}

// ---------------- tiny kernels ---------------------------------------------
__global__ void zero_pad_kernel() {
    int t = threadIdx.x;                 // 128 threads
    g_convx[N_ * H_ + t] = 0.f;
    g_glo  [N_ * H_ + t] = 0.f;
    g_r1   [N_ * H_ + t] = 0.f;
}

// copy with tf32 RNA rounding, float4-vectorized (n % 4 == 0)
__global__ void round_copy_kernel(const float* __restrict__ src,
                                  float* __restrict__ dst, int n4) {
    int i = blockIdx.x * blockDim.x + threadIdx.x;
    if (i >= n4) return;
    float4 v = reinterpret_cast<const float4*>(src)[i];
    v.x = rnd_tf32(v.x); v.y = rnd_tf32(v.y);
    v.z = rnd_tf32(v.z); v.w = rnd_tf32(v.w);
    reinterpret_cast<float4*>(dst)[i] = v;
}

// ---------------- generic tiled tf32 tensor-core GEMM -----------------------
// C[m,n] = epilogue( bias[n] + sum_k A[m,k] * B[k,n] )
// All A and B global operands are PRE-ROUNDED to tf32 (low mantissa bits zero),
// so fragments are fed to the MMA without any in-loop conversion.
enum { AM_DENSE = 0, AM_GATHER = 1, AM_CONCAT = 2 };
enum { EP_SPLIT = 0, EP_RELU = 1, EP_R2 = 2, EP_GLO = 3, EP_FINAL = 4 };

constexpr int TILE = 128;
constexpr int BK   = 32;
constexpr int PA   = BK + 4;     // 36 floats: conflict-free frag reads, 16B-aligned rows
constexpr int PB   = TILE + 8;   // 136 floats

constexpr int SMEM_BYTES = 2 * TILE * PA * 4   // As double-buffered
                         + 2 * BK * PB * 4     // Bs double-buffered
                         + TILE * K_ * 4;      // snbr

template <int AMODE, int EPI, int RND>
__global__ void __launch_bounds__(256, 2)
gemm_kernel(const float* __restrict__ A, const float* __restrict__ A2,
            const int* __restrict__ nbr,
            const float* __restrict__ Bm, int ldb, int Kdim, int lda,
            const float* __restrict__ bias,
            const float* __restrict__ aux,
            float* __restrict__ C, float* __restrict__ C2)
{
    extern __shared__ char smem_raw[];
    float* As   = reinterpret_cast<float*>(smem_raw);            // [2][128][PA]
    float* Bs   = As + 2 * TILE * PA;                            // [2][32][PB]
    int*   snbr = reinterpret_cast<int*>(Bs + 2 * BK * PB);      // [128][27]

    const int tid = threadIdx.x;
    const int m0  = blockIdx.x * TILE;
    const int n0  = blockIdx.y * TILE;

    const int lane = tid & 31;
    const int wid  = tid >> 5;         // 0..7
    const int wm   = wid & 3;          // warp row  (4 x 32 = 128)
    const int wn   = wid >> 2;         // warp col  (2 x 64 = 128)
    const int g    = lane >> 2;        // group 0..7
    const int tg   = lane & 3;         // thread-in-group 0..3

    if (AMODE == AM_GATHER) {
        for (int i = tid; i < TILE * K_; i += 256) {
            int r = i / K_, k = i % K_;
            int row = m0 + r;
            snbr[i] = (row < N_) ? nbr[row * K_ + k] : N_;   // N_ -> zero row
        }
        __syncthreads();
    }

    // --- stage one (A,B) tile pair into buffer `buf` via cp.async -----------
    auto stage = [&](int k0, int buf) {
        float* Ab = As + buf * TILE * PA;
        float* Bb = Bs + buf * BK * PB;
        // A tile: 128 rows x 32 cols = 1024 float4
#pragma unroll
        for (int it = 0; it < 4; it++) {
            int idx = tid + it * 256;
            int r   = idx >> 3;            // 0..127
            int c4  = (idx & 7) << 2;      // 0..28
            uint32_t dst = (uint32_t)__cvta_generic_to_shared(&Ab[r * PA + c4]);
            if (AMODE == AM_GATHER) {
                int kidx = k0 >> 7;                 // neighbor slot
                int cc   = (k0 & 127) + c4;
                int src  = snbr[r * K_ + kidx];
                cp16(dst, A + (size_t)src * H_ + cc, true);
            } else if (AMODE == AM_DENSE) {
                int row = m0 + r;
                cp16(dst, A + (size_t)row * lda + k0 + c4, row < N_);
            } else {  // AM_CONCAT
                int row = m0 + r;
                int gc  = k0 + c4;
                const float* srcp = (gc < H_) ? A : A2;
                int cc = (gc < H_) ? gc : gc - H_;
                cp16(dst, srcp + (size_t)row * H_ + cc, row < N_);
            }
        }
        // B tile: 32 rows x 128 cols = 1024 float4
#pragma unroll
        for (int it = 0; it < 4; it++) {
            int idx = tid + it * 256;
            int r   = idx >> 5;            // 0..31
            int c4  = (idx & 31) << 2;     // 0..124
            uint32_t dst = (uint32_t)__cvta_generic_to_shared(&Bb[r * PB + c4]);
            cp16(dst, Bm + (size_t)(k0 + r) * ldb + n0 + c4, true);
        }
    };

    float acc[2][8][4];
#pragma unroll
    for (int mt = 0; mt < 2; mt++)
#pragma unroll
        for (int nt = 0; nt < 8; nt++)
#pragma unroll
            for (int j = 0; j < 4; j++) acc[mt][nt][j] = 0.f;

    const int niter = Kdim / BK;

    stage(0, 0);
    cp_commit();

    int buf = 0;
    for (int i = 0; i < niter; i++) {
        cp_wait0();
        __syncthreads();
        if (i + 1 < niter) {
            stage((i + 1) * BK, buf ^ 1);
            cp_commit();
        }

        // operands are pre-rounded tf32 bit patterns: no cvt in the loop
        const uint32_t* Ab =
            reinterpret_cast<const uint32_t*>(As + buf * TILE * PA);
        const uint32_t* Bb =
            reinterpret_cast<const uint32_t*>(Bs + buf * BK * PB);
#pragma unroll
        for (int ks = 0; ks < BK; ks += 8) {
            uint32_t bfr[8][2];
#pragma unroll
            for (int nt = 0; nt < 8; nt++) {
                int n = wn * 64 + nt * 8 + g;
                bfr[nt][0] = Bb[(ks + tg)     * PB + n];
                bfr[nt][1] = Bb[(ks + tg + 4) * PB + n];
            }
#pragma unroll
            for (int mt = 0; mt < 2; mt++) {
                int m = wm * 32 + mt * 16 + g;
                uint32_t af[4];
                af[0] = Ab[m       * PA + ks + tg];
                af[1] = Ab[(m + 8) * PA + ks + tg];
                af[2] = Ab[m       * PA + ks + tg + 4];
                af[3] = Ab[(m + 8) * PA + ks + tg + 4];
#pragma unroll
                for (int nt = 0; nt < 8; nt++)
                    mma_tf32(acc[mt][nt], af, bfr[nt]);
            }
        }
        buf ^= 1;
    }

    // ---- epilogue: each thread owns 2x(2 rows) x 8x(2 cols) ----
    // RND=1: store tf32-rounded values (buffer is a future GEMM A-operand)
#pragma unroll
    for (int mt = 0; mt < 2; mt++) {
#pragma unroll
        for (int half = 0; half < 2; half++) {
            int row = m0 + wm * 32 + mt * 16 + g + half * 8;
            if (row >= N_) continue;
#pragma unroll
            for (int nt = 0; nt < 8; nt++) {
                int col = n0 + wn * 64 + nt * 8 + tg * 2;
                float v0 = acc[mt][nt][half * 2 + 0] + bias[col];
                float v1 = acc[mt][nt][half * 2 + 1] + bias[col + 1];
                if (EPI == EP_SPLIT) {
                    float o0 = RND ? rnd_tf32(v0) : v0;
                    float o1 = RND ? rnd_tf32(v1) : v1;
                    if (col < H_) {
                        C [(size_t)row * H_ + col]     = o0;
                        C [(size_t)row * H_ + col + 1] = o1;
                    } else {
                        C2[(size_t)row * H_ + col - H_]     = o0;
                        C2[(size_t)row * H_ + col - H_ + 1] = o1;
                    }
                } else if (EPI == EP_RELU) {
                    float o0 = fmaxf(v0, 0.f), o1 = fmaxf(v1, 0.f);
                    if (RND) { o0 = rnd_tf32(o0); o1 = rnd_tf32(o1); }
                    *reinterpret_cast<float2*>(C + (size_t)row * H_ + col) =
                        make_float2(o0, o1);
                } else if (EPI == EP_R2) {
                    float2 a = *reinterpret_cast<const float2*>(
                        aux + (size_t)row * H_ + col);
                    float o0 = fmaxf(v0, 0.f) + 2.f * a.x;
                    float o1 = fmaxf(v1, 0.f) + 2.f * a.y;
                    if (RND) { o0 = rnd_tf32(o0); o1 = rnd_tf32(o1); }
                    *reinterpret_cast<float2*>(C + (size_t)row * H_ + col) =
                        make_float2(o0, o1);
                } else if (EPI == EP_GLO) {
                    float2 a = *reinterpret_cast<const float2*>(
                        aux + (size_t)row * H_ + col);
                    float o0 = fmaxf(a.x - fmaxf(v0, 0.f), 0.f);
                    float o1 = fmaxf(a.y - fmaxf(v1, 0.f), 0.f);
                    if (RND) { o0 = rnd_tf32(o0); o1 = rnd_tf32(o1); }
                    *reinterpret_cast<float2*>(C + (size_t)row * H_ + col) =
                        make_float2(o0, o1);
                } else {  // EP_FINAL
                    float2 a = *reinterpret_cast<const float2*>(
                        aux + (size_t)row * DIM_ + col);
                    *reinterpret_cast<float2*>(C + (size_t)row * DIM_ + col) =
                        make_float2(a.x + v0, a.y + v1);
                }
            }
        }
    }
}

// ---------------- deterministic segment mean (m2) ---------------------------
__global__ void seg_partial_kernel(const int* __restrict__ bids) {
    int blk = blockIdx.x;
    int o   = threadIdx.x;            // 128 threads = one column each
    int r0  = blk * CHUNK;
    int r1  = min(r0 + CHUNK, N_);
    float a0 = 0.f, a1 = 0.f, a2 = 0.f, a3 = 0.f;
    for (int r = r0; r < r1; r++) {
        int   b = bids[r];
        float v = g_f2[(size_t)r * H_ + o];
        a0 += (b == 0) ? v : 0.f;
        a1 += (b == 1) ? v : 0.f;
        a2 += (b == 2) ? v : 0.f;
        a3 += (b == 3) ? v : 0.f;
    }
    g_part[(blk * B_ + 0) * H_ + o] = a0;
    g_part[(blk * B_ + 1) * H_ + o] = a1;
    g_part[(blk * B_ + 2) * H_ + o] = a2;
    g_part[(blk * B_ + 3) * H_ + o] = a3;
    if (o < B_) {
        int c = 0;
        for (int r = r0; r < r1; r++) c += (bids[r] == o);
        g_cnt[blk * B_ + o] = c;
    }
}

__global__ void seg_final_kernel() {
    int t = threadIdx.x;              // 512 threads = (b,o)
    float s = 0.f;
    for (int p = 0; p < NPART; p++) s += g_part[p * B_ * H_ + t];
    __shared__ int scnt[B_];
    if (t < B_) {
        int c = 0;
        for (int p = 0; p < NPART; p++) c += g_cnt[p * B_ + t];
        scnt[t] = c;
    }
    __syncthreads();
    int b = t / H_;
    float cnt = (float)max(scnt[b], 1);
    g_m2[t] = s / cnt;
}

// ---------------- enc / t = enc + f1 + f2 (stores tf32-rounded) -------------
__global__ void enc_kernel(const int* __restrict__ bids) {
    int warp = threadIdx.x >> 5;      // 4 warps -> 4 rows per block
    int lane = threadIdx.x & 31;
    int row  = blockIdx.x * 4 + warp;

    float4 f1v = reinterpret_cast<const float4*>(g_f1 + (size_t)row * H_)[lane];
    float s = f1v.x + f1v.y + f1v.z + f1v.w;
#pragma unroll
    for (int off = 16; off; off >>= 1) s += __shfl_xor_sync(0xffffffffu, s, off);
    float row1 = s * (1.f / 128.f);

    int b = bids[row];
    float4 f2v = reinterpret_cast<const float4*>(g_f2 + (size_t)row * H_)[lane];
    float4 m2v = reinterpret_cast<const float4*>(g_m2 + b * H_)[lane];

    float4 t;
    t.x = rnd_tf32(sqrtf(row1 * m2v.x + 1e-12f) + f1v.x + f2v.x);
    t.y = rnd_tf32(sqrtf(row1 * m2v.y + 1e-12f) + f1v.y + f2v.y);
    t.z = rnd_tf32(sqrtf(row1 * m2v.z + 1e-12f) + f1v.z + f2v.z);
    t.w = rnd_tf32(sqrtf(row1 * m2v.w + 1e-12f) + f1v.w + f2v.w);
    reinterpret_cast<float4*>(g_t + (size_t)row * H_)[lane] = t;
}

// ---------------- launch ----------------------------------------------------
static inline void round_copy(const float* src, float* dst, int n) {
    int n4 = n / 4;
    round_copy_kernel<<<(n4 + 255) / 256, 256>>>(src, dst, n4);
}

extern "C" void kernel_launch(void* const* d_in, const int* in_sizes, int n_in,
                              void* d_out, int out_size)
{
    const float* x    = (const float*)d_in[0];
    const int*   nbr  = (const int*)  d_in[1];
    const int*   bids = (const int*)  d_in[2];
    const float* W1   = (const float*)d_in[3];
    const float* b1   = (const float*)d_in[4];
    const float* W2   = (const float*)d_in[5];
    const float* b2   = (const float*)d_in[6];
    const float* Wr1  = (const float*)d_in[7];
    const float* br1  = (const float*)d_in[8];
    const float* Wr2  = (const float*)d_in[9];
    const float* br2  = (const float*)d_in[10];
    const float* Wg1  = (const float*)d_in[11];
    const float* bg1  = (const float*)d_in[12];
    const float* Wg2  = (const float*)d_in[13];
    const float* bg2  = (const float*)d_in[14];
    const float* Wg3  = (const float*)d_in[15];
    const float* bg3  = (const float*)d_in[16];
    float* out = (float*)d_out;

    float *convx, *glo, *r1, *convout, *f1, *f2, *tb;
    float *xr, *W1r, *W2r, *Wr1r, *Wr2r, *Wg1r, *Wg2r, *Wg3r;
    cudaGetSymbolAddress((void**)&convx,   g_convx);
    cudaGetSymbolAddress((void**)&glo,     g_glo);
    cudaGetSymbolAddress((void**)&r1,      g_r1);
    cudaGetSymbolAddress((void**)&convout, g_convout);
    cudaGetSymbolAddress((void**)&f1,      g_f1);
    cudaGetSymbolAddress((void**)&f2,      g_f2);
    cudaGetSymbolAddress((void**)&tb,      g_t);
    cudaGetSymbolAddress((void**)&xr,      g_xr);
    cudaGetSymbolAddress((void**)&W1r,     g_W1r);
    cudaGetSymbolAddress((void**)&W2r,     g_W2r);
    cudaGetSymbolAddress((void**)&Wr1r,    g_Wr1r);
    cudaGetSymbolAddress((void**)&Wr2r,    g_Wr2r);
    cudaGetSymbolAddress((void**)&Wg1r,    g_Wg1r);
    cudaGetSymbolAddress((void**)&Wg2r,    g_Wg2r);
    cudaGetSymbolAddress((void**)&Wg3r,    g_Wg3r);

    // allow >48KB dynamic smem on every instantiation (idempotent, host-side)
    cudaFuncSetAttribute(gemm_kernel<AM_DENSE,  EP_SPLIT, 1>,
                         cudaFuncAttributeMaxDynamicSharedMemorySize, SMEM_BYTES);
    cudaFuncSetAttribute(gemm_kernel<AM_GATHER, EP_RELU,  1>,
                         cudaFuncAttributeMaxDynamicSharedMemorySize, SMEM_BYTES);
    cudaFuncSetAttribute(gemm_kernel<AM_GATHER, EP_RELU,  0>,
                         cudaFuncAttributeMaxDynamicSharedMemorySize, SMEM_BYTES);
    cudaFuncSetAttribute(gemm_kernel<AM_GATHER, EP_R2,    1>,
                         cudaFuncAttributeMaxDynamicSharedMemorySize, SMEM_BYTES);
    cudaFuncSetAttribute(gemm_kernel<AM_DENSE,  EP_GLO,   1>,
                         cudaFuncAttributeMaxDynamicSharedMemorySize, SMEM_BYTES);
    cudaFuncSetAttribute(gemm_kernel<AM_CONCAT, EP_FINAL, 0>,
                         cudaFuncAttributeMaxDynamicSharedMemorySize, SMEM_BYTES);

    const int mt = (N_ + TILE - 1) / TILE;   // 313
    dim3 blk(256);

    // ---- prep: tf32-round all static GEMM operands ----
    round_copy(x,   xr,   N_ * DIM_);
    round_copy(W1,  W1r,  DIM_ * DIM_);
    round_copy(W2,  W2r,  DIM_ * DIM_);
    round_copy(Wr1, Wr1r, KH_ * H_);
    round_copy(Wr2, Wr2r, KH_ * H_);
    round_copy(Wg1, Wg1r, KH_ * H_);
    round_copy(Wg2, Wg2r, KH_ * H_);
    round_copy(Wg3, Wg3r, H_ * H_);

    // zero the padding row of all gathered buffers
    zero_pad_kernel<<<1, 128>>>();

    // h = x@W1 + b1 ; conv_x = h[:, :128] ; glo = h[:, 128:]  (stored rounded)
    gemm_kernel<AM_DENSE, EP_SPLIT, 1><<<dim3(mt, 2), blk, SMEM_BYTES>>>(
        xr, nullptr, nullptr, W1r, DIM_, DIM_, DIM_, b1, nullptr, convx, glo);

    // r1 = relu(sconv(conv_x, Wr1, br1))   (stored rounded)
    gemm_kernel<AM_GATHER, EP_RELU, 1><<<dim3(mt, 1), blk, SMEM_BYTES>>>(
        convx, nullptr, nbr, Wr1r, H_, KH_, 0, br1, nullptr, r1, nullptr);

    // convout = relu(sconv(r1, Wr2, br2)) + 2*conv_x   (stored rounded)
    gemm_kernel<AM_GATHER, EP_R2, 1><<<dim3(mt, 1), blk, SMEM_BYTES>>>(
        r1, nullptr, nbr, Wr2r, H_, KH_, 0, br2, convx, convout, nullptr);

    // f1 / f2 (unrounded: consumed by exact seg/enc path)
    gemm_kernel<AM_GATHER, EP_RELU, 0><<<dim3(mt, 1), blk, SMEM_BYTES>>>(
        glo, nullptr, nbr, Wg1r, H_, KH_, 0, bg1, nullptr, f1, nullptr);
    gemm_kernel<AM_GATHER, EP_RELU, 0><<<dim3(mt, 1), blk, SMEM_BYTES>>>(
        glo, nullptr, nbr, Wg2r, H_, KH_, 0, bg2, nullptr, f2, nullptr);

    // m2 = segment_mean(f2) (deterministic two-pass)
    seg_partial_kernel<<<NPART, 128>>>(bids);
    seg_final_kernel<<<1, 512>>>();

    // t = sqrt(mean(f1)*m2[bid] + 1e-12) + f1 + f2   (stored rounded)
    enc_kernel<<<N_ / 4, 128>>>(bids);

    // glo = relu(glo - relu(t@Wg3 + bg3))   (stored rounded)
    gemm_kernel<AM_DENSE, EP_GLO, 1><<<dim3(mt, 1), blk, SMEM_BYTES>>>(
        tb, nullptr, nullptr, Wg3r, H_, H_, H_, bg3, glo, glo, nullptr);

    // out = x + [convout | glo] @ W2 + b2
    gemm_kernel<AM_CONCAT, EP_FINAL, 0><<<dim3(mt, 2), blk, SMEM_BYTES>>>(
        convout, glo, nullptr, W2r, DIM_, DIM_, 0, b2, x, out, nullptr);
}